// round 16
// baseline (speedup 1.0000x reference)
#include <cuda_runtime.h>

// Fixed shapes: B=64, P=68, H=W=64 -> 4352 tiles of 4096 pixels
// Two tiles per 512-thread block: half-block (256 thr) per tile.
#define HW       4096
#define NTHREADS 512
#define HALF     256
#define NWARPS_H 8            // warps per half
#define EPS      1e-5f
#define LOG2E    1.4426950408889634f
#define LN2      0.6931471805599453f

// Raw MUFU intrinsics (exp2f/log2f are PRECISE libm without -use_fast_math)
__device__ __forceinline__ float ex2(float x) {
    float r; asm("ex2.approx.ftz.f32 %0, %1;" : "=f"(r) : "f"(x)); return r;
}
__device__ __forceinline__ float lg2(float x) {
    float r; asm("lg2.approx.f32 %0, %1;" : "=f"(r) : "f"(x)); return r;
}

__global__ __launch_bounds__(NTHREADS)
void gauss_kl_kernel(const float* __restrict__ hm,
                     const float2* __restrict__ means,  // [B*P] float2
                     const float4* __restrict__ cov,    // [B*P] float4
                     float* __restrict__ out,
                     float scale)                       // LN2 / n_tiles
{
    // e values in SMEM (no register spills); one 16KB bank per half-block
    __shared__ float4 se[2][4][HALF];                   // 32 KB
    __shared__ float  ws[2][NWARPS_H];
    __shared__ float  wa[2][NWARPS_H];

    const int tid  = threadIdx.x;
    const int half = tid >> 8;           // 0 or 1: which tile
    const int ltid = tid & (HALF - 1);   // thread id within the half
    const int bp   = blockIdx.x * 2 + half;

    // Front-batch the 4 streaming LDG.128 loads (latency hidden under pass 1)
    const float4* hm4 = reinterpret_cast<const float4*>(hm + (size_t)bp * HW);
    float4 h[4];
#pragma unroll
    for (int k = 0; k < 4; k++) h[k] = __ldcs(&hm4[ltid + k * HALF]);

    // Per-tile Gaussian parameters: ONE LDG.64 + ONE LDG.128
    const float2 mn = __ldg(&means[bp]);
    const float4 sg = __ldg(&cov[bp]);
    const float det = fmaf(sg.x, sg.w, -sg.y * sg.z) + EPS;
    const float inv_det = LOG2E / det;
    // lp = log2(exp(-quad/2)) = Ac*dx^2 + Bc*dx*dy + Cc*dy^2
    const float Ac = -0.5f * sg.w * inv_det;
    const float Bc =  0.5f * (sg.y + sg.z) * inv_det;
    const float Cc = -0.5f * sg.x * inv_det;

    // Geometry: i4 = ltid + 256k -> row = (ltid>>4) + 16k, x0 = (ltid&15)*4
    const float xm  = (float)((ltid & 15) << 2) - mn.x;
    const float dx0 = xm,        dx1 = xm + 1.0f;
    const float dx2 = xm + 2.0f, dx3 = xm + 3.0f;
    const float dyb = (float)(ltid >> 4) - mn.y;

    // Pass 1: e = 2^lp (EX2) -> STS.128; S via two independent accumulators
    float S0 = 0.0f, S1 = 0.0f;
#pragma unroll
    for (int k = 0; k < 4; k++) {
        const float dy   = dyb + (float)(16 * k);
        const float bdy  = Bc * dy;
        const float cdy2 = (Cc * dy) * dy;
        float4 ev;
        ev.x = ex2(fmaf(fmaf(Ac, dx0, bdy), dx0, cdy2));
        ev.y = ex2(fmaf(fmaf(Ac, dx1, bdy), dx1, cdy2));
        ev.z = ex2(fmaf(fmaf(Ac, dx2, bdy), dx2, cdy2));
        ev.w = ex2(fmaf(fmaf(Ac, dx3, bdy), dx3, cdy2));
        se[half][k][ltid] = ev;                  // conflict-free STS.128
        if (k & 1) S1 += (ev.x + ev.y) + (ev.z + ev.w);
        else       S0 += (ev.x + ev.y) + (ev.z + ev.w);
    }
    float S = S0 + S1;

    // Reduce S within the half: warp shfl, lane0 -> smem, ONE shared barrier
    const int wid = (ltid >> 5), lid = tid & 31;    // warp index within half
#pragma unroll
    for (int o = 16; o > 0; o >>= 1) S += __shfl_xor_sync(0xffffffffu, S, o);
    if (lid == 0) ws[half][wid] = S;
    __syncthreads();                                 // serves BOTH tiles
    const float* wsh = ws[half];
    const float Sfull = ((wsh[0] + wsh[1]) + (wsh[2] + wsh[3]))
                      + ((wsh[4] + wsh[5]) + (wsh[6] + wsh[7]));
    const float c = EPS * Sfull;                     // pr + eps = (e + c)/S

    // Pass 2: two independent FMA chains:
    //   accH = sum h*lg2(h)      accT = sum h*lg2(e+c)
    float accH = 0.0f, accT = 0.0f;
#pragma unroll
    for (int k = 0; k < 4; k++) {
        const float4 hv = h[k];
        const float4 ev = se[half][k][ltid];
        accH = fmaf(hv.x, lg2(hv.x), accH);
        accT = fmaf(hv.x, lg2(ev.x + c), accT);
        accH = fmaf(hv.y, lg2(hv.y), accH);
        accT = fmaf(hv.y, lg2(ev.y + c), accT);
        accH = fmaf(hv.z, lg2(hv.z), accH);
        accT = fmaf(hv.z, lg2(ev.z + c), accT);
        accH = fmaf(hv.w, lg2(hv.w), accH);
        accT = fmaf(hv.w, lg2(ev.w + c), accT);
    }
    float acc = accH - accT;

    // Reduce acc within the half; ltid==0 finishes its tile
#pragma unroll
    for (int o = 16; o > 0; o >>= 1) acc += __shfl_xor_sync(0xffffffffu, acc, o);
    if (lid == 0) wa[half][wid] = acc;
    __syncthreads();                                 // serves BOTH tiles
    if (ltid == 0) {
        const float* wah = wa[half];
        const float v = ((wah[0] + wah[1]) + (wah[2] + wah[3]))
                      + ((wah[4] + wah[5]) + (wah[6] + wah[7]));
        // loss_tile = ln2 * (acc + lg2(S))   [sum(hm) == 1 per tile]
        atomicAdd(out, scale * (v + lg2(Sfull)));
    }
}

extern "C" void kernel_launch(void* const* d_in, const int* in_sizes, int n_in,
                              void* d_out, int out_size)
{
    const float*  hm    = (const float*)d_in[0];   // [B,P,H,W]
    const float2* means = (const float2*)d_in[1];  // [B,P,2]
    const float4* cov   = (const float4*)d_in[2];  // [B,P,4]
    float* out = (float*)d_out;

    const int n_bp = in_sizes[1] / 2;              // 4352 (even)

    cudaMemsetAsync(out, 0, (size_t)out_size * sizeof(float));
    gauss_kl_kernel<<<n_bp / 2, NTHREADS>>>(hm, means, cov, out,
                                            LN2 / (float)n_bp);
}

// round 17
// speedup vs baseline: 1.1920x; 1.1920x over previous
#include <cuda_runtime.h>

// Fixed shapes: B=64, P=68, H=W=64 -> 4352 tiles of 4096 pixels
#define HW       4096
#define NTHREADS 256
#define NWARPS   8
#define EPS      1e-5f
#define LOG2E    1.4426950408889634f
#define LN2      0.6931471805599453f

// Raw MUFU intrinsics. NOTE: .ftz on BOTH — without .ftz, ptxas wraps
// lg2.approx in a denormal-guard sequence (~3 extra instr per call, 32
// calls/thread). Operands here are provably normal (h >= ~5e-7,
// e+c >= c ~ 8e-6), so .ftz is exact.
__device__ __forceinline__ float ex2(float x) {
    float r; asm("ex2.approx.ftz.f32 %0, %1;" : "=f"(r) : "f"(x)); return r;
}
__device__ __forceinline__ float lg2(float x) {
    float r; asm("lg2.approx.ftz.f32 %0, %1;" : "=f"(r) : "f"(x)); return r;
}

__global__ __launch_bounds__(NTHREADS)
void gauss_kl_kernel(const float* __restrict__ hm,
                     const float2* __restrict__ means,  // [B*P] float2
                     const float4* __restrict__ cov,    // [B*P] float4
                     float* __restrict__ out,
                     float scale)                       // LN2 / n_tiles
{
    // e values live in SMEM (keeps regs ~40, occ ~65%)
    __shared__ float4 se[4][NTHREADS];                  // 16 KB
    __shared__ float  ws[NWARPS];
    __shared__ float  wa[NWARPS];

    const int bp  = blockIdx.x;
    const int tid = threadIdx.x;

    // Front-batch the 4 streaming LDG.128 loads (latency hidden under pass 1)
    const float4* hm4 = reinterpret_cast<const float4*>(hm + (size_t)bp * HW);
    float4 h[4];
#pragma unroll
    for (int k = 0; k < 4; k++) h[k] = __ldcs(&hm4[tid + k * NTHREADS]);

    // Per-tile Gaussian parameters: ONE LDG.64 + ONE LDG.128
    const float2 mn = __ldg(&means[bp]);
    const float4 sg = __ldg(&cov[bp]);
    const float det = fmaf(sg.x, sg.w, -sg.y * sg.z) + EPS;
    const float inv_det = LOG2E / det;
    // lp = log2(exp(-quad/2)) = Ac*dx^2 + Bc*dx*dy + Cc*dy^2
    const float Ac = -0.5f * sg.w * inv_det;
    const float Bc =  0.5f * (sg.y + sg.z) * inv_det;
    const float Cc = -0.5f * sg.x * inv_det;

    // Geometry: i4 = tid + 256k -> row = (tid>>4) + 16k, x0 = (tid&15)*4
    const float xm  = (float)((tid & 15) << 2) - mn.x;
    const float dx0 = xm,        dx1 = xm + 1.0f;
    const float dx2 = xm + 2.0f, dx3 = xm + 3.0f;
    const float dyb = (float)(tid >> 4) - mn.y;

    // Pass 1: e = 2^lp (EX2) -> STS.128; S via two independent accumulators
    float S0 = 0.0f, S1 = 0.0f;
#pragma unroll
    for (int k = 0; k < 4; k++) {
        const float dy   = dyb + (float)(16 * k);
        const float bdy  = Bc * dy;
        const float cdy2 = (Cc * dy) * dy;
        float4 ev;
        ev.x = ex2(fmaf(fmaf(Ac, dx0, bdy), dx0, cdy2));
        ev.y = ex2(fmaf(fmaf(Ac, dx1, bdy), dx1, cdy2));
        ev.z = ex2(fmaf(fmaf(Ac, dx2, bdy), dx2, cdy2));
        ev.w = ex2(fmaf(fmaf(Ac, dx3, bdy), dx3, cdy2));
        se[k][tid] = ev;                     // conflict-free STS.128
        if (k & 1) S1 += (ev.x + ev.y) + (ev.z + ev.w);
        else       S0 += (ev.x + ev.y) + (ev.z + ev.w);
    }
    float S = S0 + S1;

    // Reduce S: warp shfl, lane0 -> smem, ONE barrier, all threads sum partials
    const int wid = tid >> 5, lid = tid & 31;
#pragma unroll
    for (int o = 16; o > 0; o >>= 1) S += __shfl_xor_sync(0xffffffffu, S, o);
    if (lid == 0) ws[wid] = S;
    __syncthreads();
    const float Sfull = ((ws[0] + ws[1]) + (ws[2] + ws[3]))
                      + ((ws[4] + ws[5]) + (ws[6] + ws[7]));
    const float c = EPS * Sfull;             // pr + eps = (e + c)/S

    // Pass 2: two independent FMA chains:
    //   accH = sum h*lg2(h)      accT = sum h*lg2(e+c)
    float accH = 0.0f, accT = 0.0f;
#pragma unroll
    for (int k = 0; k < 4; k++) {
        const float4 hv = h[k];
        const float4 ev = se[k][tid];
        accH = fmaf(hv.x, lg2(hv.x), accH);
        accT = fmaf(hv.x, lg2(ev.x + c), accT);
        accH = fmaf(hv.y, lg2(hv.y), accH);
        accT = fmaf(hv.y, lg2(ev.y + c), accT);
        accH = fmaf(hv.z, lg2(hv.z), accH);
        accT = fmaf(hv.z, lg2(ev.z + c), accT);
        accH = fmaf(hv.w, lg2(hv.w), accH);
        accT = fmaf(hv.w, lg2(ev.w + c), accT);
    }
    float acc = accH - accT;

    // Reduce acc; tid0 finishes tile and RED.ADDs into out
#pragma unroll
    for (int o = 16; o > 0; o >>= 1) acc += __shfl_xor_sync(0xffffffffu, acc, o);
    if (lid == 0) wa[wid] = acc;
    __syncthreads();
    if (tid == 0) {
        const float v = ((wa[0] + wa[1]) + (wa[2] + wa[3]))
                      + ((wa[4] + wa[5]) + (wa[6] + wa[7]));
        // loss_tile = ln2 * (acc + lg2(S))   [sum(hm) == 1 per tile]
        atomicAdd(out, scale * (v + lg2(Sfull)));
    }
}

extern "C" void kernel_launch(void* const* d_in, const int* in_sizes, int n_in,
                              void* d_out, int out_size)
{
    const float*  hm    = (const float*)d_in[0];   // [B,P,H,W]
    const float2* means = (const float2*)d_in[1];  // [B,P,2]
    const float4* cov   = (const float4*)d_in[2];  // [B,P,4]
    float* out = (float*)d_out;

    const int n_bp = in_sizes[1] / 2;              // 4352

    cudaMemsetAsync(out, 0, (size_t)out_size * sizeof(float));
    gauss_kl_kernel<<<n_bp, NTHREADS>>>(hm, means, cov, out,
                                        LN2 / (float)n_bp);
}